// round 3
// baseline (speedup 1.0000x reference)
#include <cuda_runtime.h>
#include <cuda_bf16.h>

#define N_NODES  40000
#define N_EDGES  640000
#define HID      128
#define N_GRAPHS 256

// ---------------- scratch (no allocation allowed) ----------------
__device__ float g_bufA[N_NODES * HID];   // hw (gemm output)
__device__ float g_bufB[N_NODES * HID];   // agg layer 1
__device__ float g_bufC[N_NODES * HID];   // agg layer 2
__device__ float g_deg_out[N_NODES];
__device__ float g_deg_in[N_NODES];
__device__ float g_hg[N_GRAPHS * HID];
__device__ float g_cnt[N_GRAPHS];

// ---------------- zeroing ----------------
__global__ void zero2_k(float4* a, float4* b, int n4) {
    int i = blockIdx.x * blockDim.x + threadIdx.x;
    if (i < n4) {
        a[i] = make_float4(0.f, 0.f, 0.f, 0.f);
        b[i] = make_float4(0.f, 0.f, 0.f, 0.f);
    }
}

__global__ void zero_misc_k() {
    int i = blockIdx.x * blockDim.x + threadIdx.x;
    if (i < N_NODES) { g_deg_out[i] = 0.f; g_deg_in[i] = 0.f; }
    if (i < N_GRAPHS * HID) g_hg[i] = 0.f;
    if (i < N_GRAPHS) g_cnt[i] = 0.f;
}

// ---------------- degrees ----------------
__global__ void degree_k(const int* __restrict__ src, const int* __restrict__ dst) {
    int e = blockIdx.x * blockDim.x + threadIdx.x;
    if (e < N_EDGES) {
        atomicAdd(&g_deg_out[src[e]], 1.f);
        atomicAdd(&g_deg_in[dst[e]], 1.f);
    }
}

// ---------------- GEMM: out[M,128] = transform(in)[M,128] @ W[128,128] ----------------
// transform (bprev == null):  v = in * ns(row)
// transform (bprev != null):  v = relu(in * nd(row) + bprev[col]) * ns(row)
#define KC 16
__global__ __launch_bounds__(256) void gemm_k(
    const float* __restrict__ in, const float* __restrict__ W,
    const float* __restrict__ bprev, float* __restrict__ out)
{
    __shared__ float sA[KC][HID + 4];
    __shared__ float sW[KC][HID];
    __shared__ float sNs[HID];
    __shared__ float sNd[HID];

    const int tid = threadIdx.x;
    const int tx = tid & 15;     // 0..15 -> columns
    const int ty = tid >> 4;     // 0..15 -> rows
    const int row0 = blockIdx.x * 128;

    if (tid < 128) {
        int r = row0 + tid;
        float ns = 0.f, nd = 0.f;
        if (r < N_NODES) {
            ns = rsqrtf(fmaxf(g_deg_out[r], 1.f));
            nd = rsqrtf(fmaxf(g_deg_in[r], 1.f));
        }
        sNs[tid] = ns;
        sNd[tid] = nd;
    }
    __syncthreads();

    float acc[8][8];
#pragma unroll
    for (int i = 0; i < 8; i++)
#pragma unroll
        for (int j = 0; j < 8; j++) acc[i][j] = 0.f;

    for (int k0 = 0; k0 < HID; k0 += KC) {
        // load A tile (128 rows x 16 k), transposed into sA[k][row], transform fused
#pragma unroll
        for (int t = 0; t < 2; t++) {
            int l = tid + t * 256;        // 0..511
            int r = l >> 2;               // 0..127
            int kq = (l & 3) * 4;         // 0,4,8,12
            int grow = row0 + r;
            float4 v = make_float4(0.f, 0.f, 0.f, 0.f);
            if (grow < N_NODES) {
                v = *(const float4*)&in[grow * HID + k0 + kq];
                float ns = sNs[r];
                if (bprev) {
                    float nd = sNd[r];
                    float4 b = *(const float4*)&bprev[k0 + kq];
                    v.x = fmaxf(v.x * nd + b.x, 0.f);
                    v.y = fmaxf(v.y * nd + b.y, 0.f);
                    v.z = fmaxf(v.z * nd + b.z, 0.f);
                    v.w = fmaxf(v.w * nd + b.w, 0.f);
                }
                v.x *= ns; v.y *= ns; v.z *= ns; v.w *= ns;
            }
            sA[kq + 0][r] = v.x;
            sA[kq + 1][r] = v.y;
            sA[kq + 2][r] = v.z;
            sA[kq + 3][r] = v.w;
        }
        // load W tile (16 k x 128 cols), direct
#pragma unroll
        for (int t = 0; t < 2; t++) {
            int l = tid + t * 256;        // 0..511
            int kk = l >> 5;              // 0..15
            int n4 = (l & 31) * 4;        // 0..124
            *(float4*)&sW[kk][n4] = *(const float4*)&W[(k0 + kk) * HID + n4];
        }
        __syncthreads();

#pragma unroll
        for (int kk = 0; kk < KC; kk++) {
            float4 a0 = *(const float4*)&sA[kk][ty * 4];
            float4 a1 = *(const float4*)&sA[kk][ty * 4 + 64];
            float4 w0 = *(const float4*)&sW[kk][tx * 4];
            float4 w1 = *(const float4*)&sW[kk][tx * 4 + 64];
            float a[8] = {a0.x, a0.y, a0.z, a0.w, a1.x, a1.y, a1.z, a1.w};
            float w[8] = {w0.x, w0.y, w0.z, w0.w, w1.x, w1.y, w1.z, w1.w};
#pragma unroll
            for (int i = 0; i < 8; i++)
#pragma unroll
                for (int j = 0; j < 8; j++)
                    acc[i][j] += a[i] * w[j];
        }
        __syncthreads();
    }

    // epilogue
#pragma unroll
    for (int i = 0; i < 8; i++) {
        int r = row0 + ((i < 4) ? (ty * 4 + i) : (ty * 4 + 64 + i - 4));
        if (r >= N_NODES) continue;
        float4 c0 = make_float4(acc[i][0], acc[i][1], acc[i][2], acc[i][3]);
        float4 c1 = make_float4(acc[i][4], acc[i][5], acc[i][6], acc[i][7]);
        *(float4*)&out[r * HID + tx * 4] = c0;
        *(float4*)&out[r * HID + tx * 4 + 64] = c1;
    }
}

// ---------------- scatter: agg[dst[e]] += hw[src[e]] (one warp per edge) ----------------
__global__ __launch_bounds__(256) void scatter_k(
    const float* __restrict__ hw, const int* __restrict__ src,
    const int* __restrict__ dst, float* __restrict__ agg)
{
    int gt = blockIdx.x * blockDim.x + threadIdx.x;
    int e = gt >> 5;
    int lane = gt & 31;
    if (e >= N_EDGES) return;
    int s = src[e];
    int d = dst[e];
    float4 v = *(const float4*)&hw[s * HID + lane * 4];
    float* o = &agg[d * HID + lane * 4];
    atomicAdd(o + 0, v.x);
    atomicAdd(o + 1, v.y);
    atomicAdd(o + 2, v.z);
    atomicAdd(o + 3, v.w);
}

// ---------------- pooling: hg[gid[n]] += relu(agg2[n]*nd + b2) ----------------
__global__ void pool_k(const float* __restrict__ agg2, const float* __restrict__ b2,
                       const int* __restrict__ gid)
{
    int i = blockIdx.x * blockDim.x + threadIdx.x;
    if (i >= N_NODES * HID) return;
    int n = i >> 7;
    int f = i & 127;
    float nd = rsqrtf(fmaxf(g_deg_in[n], 1.f));
    float v = fmaxf(agg2[i] * nd + b2[f], 0.f);
    atomicAdd(&g_hg[gid[n] * HID + f], v);
}

__global__ void count_k(const int* __restrict__ gid) {
    int n = blockIdx.x * blockDim.x + threadIdx.x;
    if (n < N_NODES) atomicAdd(&g_cnt[gid[n]], 1.f);
}

// ---------------- MLP head: one block per graph ----------------
__global__ __launch_bounds__(128) void mlp_k(
    const float* __restrict__ Wc1, const float* __restrict__ bc1,
    const float* __restrict__ Wc2, const float* __restrict__ bc2,
    const float* __restrict__ Wc3, const float* __restrict__ bc3,
    float* __restrict__ out)
{
    int g = blockIdx.x;
    int j = threadIdx.x;
    __shared__ float sIn[HID];
    __shared__ float sMid[HID];
    __shared__ float red[4];

    float c = fmaxf(g_cnt[g], 1.f);
    sIn[j] = g_hg[g * HID + j] / c;
    __syncthreads();

    float a = bc1[j];
#pragma unroll 4
    for (int k = 0; k < HID; k++) a += sIn[k] * Wc1[k * HID + j];
    sMid[j] = fmaxf(a, 0.f);
    __syncthreads();

    float b = bc2[j];
#pragma unroll 4
    for (int k = 0; k < HID; k++) b += sMid[k] * Wc2[k * HID + j];
    b = fmaxf(b, 0.f);

    float p = b * Wc3[j];
#pragma unroll
    for (int o = 16; o > 0; o >>= 1) p += __shfl_down_sync(0xffffffffu, p, o);
    if ((j & 31) == 0) red[j >> 5] = p;
    __syncthreads();
    if (j == 0) out[g] = red[0] + red[1] + red[2] + red[3] + bc3[0];
}

// ---------------- launch ----------------
extern "C" void kernel_launch(void* const* d_in, const int* in_sizes, int n_in,
                              void* d_out, int out_size)
{
    const float* h   = (const float*)d_in[0];
    const int* src   = (const int*)d_in[1];
    const int* dst   = (const int*)d_in[2];
    const int* gid   = (const int*)d_in[3];
    const float* W1  = (const float*)d_in[4];
    const float* b1  = (const float*)d_in[5];
    const float* W2  = (const float*)d_in[6];
    const float* b2  = (const float*)d_in[7];
    const float* Wc1 = (const float*)d_in[8];
    const float* bc1 = (const float*)d_in[9];
    const float* Wc2 = (const float*)d_in[10];
    const float* bc2 = (const float*)d_in[11];
    const float* Wc3 = (const float*)d_in[12];
    const float* bc3 = (const float*)d_in[13];
    float* out = (float*)d_out;

    float *pA, *pB, *pC;
    cudaGetSymbolAddress((void**)&pA, g_bufA);
    cudaGetSymbolAddress((void**)&pB, g_bufB);
    cudaGetSymbolAddress((void**)&pC, g_bufC);

    const int n4 = N_NODES * HID / 4;          // 1,280,000 float4 per buffer
    zero2_k<<<(n4 + 255) / 256, 256>>>((float4*)pB, (float4*)pC, n4);
    zero_misc_k<<<(N_NODES + 255) / 256, 256>>>();
    degree_k<<<(N_EDGES + 255) / 256, 256>>>(src, dst);

    const int gemm_blocks = (N_NODES + 127) / 128;   // 313
    const int scat_blocks = (N_EDGES * 32 + 255) / 256;  // 80000

    // layer 1
    gemm_k<<<gemm_blocks, 256>>>(h, W1, nullptr, pA);
    scatter_k<<<scat_blocks, 256>>>(pA, src, dst, pB);

    // layer 2 (relu(agg1*nd+b1)*ns fused into loader)
    gemm_k<<<gemm_blocks, 256>>>(pB, W2, b1, pA);
    scatter_k<<<scat_blocks, 256>>>(pA, src, dst, pC);

    // pooling + head
    pool_k<<<(N_NODES * HID + 255) / 256, 256>>>(pC, b2, gid);
    count_k<<<(N_NODES + 255) / 256, 256>>>(gid);
    mlp_k<<<N_GRAPHS, 128>>>(Wc1, bc1, Wc2, bc2, Wc3, bc3, out);
}

// round 5
// speedup vs baseline: 2.2393x; 2.2393x over previous
#include <cuda_runtime.h>
#include <cuda_bf16.h>

#define N_NODES  40000
#define N_EDGES  640000
#define HID      128
#define N_GRAPHS 256

typedef unsigned long long u64;

// ---------------- scratch (no allocation allowed) ----------------
__device__ float g_bufA[N_NODES * HID];   // hw (gemm output)
__device__ float g_bufB[N_NODES * HID];   // agg layer 1
__device__ float g_bufC[N_NODES * HID];   // agg layer 2
__device__ int   g_deg_out[N_NODES];
__device__ int   g_deg_in[N_NODES];
__device__ int   g_row_ptr[N_NODES + 1];
__device__ int   g_fill[N_NODES];
__device__ int   g_csr_src[N_EDGES];

// ---------------- f32x2 helpers ----------------
__device__ __forceinline__ u64 pack2(float lo, float hi) {
    u64 r; asm("mov.b64 %0, {%1, %2};" : "=l"(r) : "f"(lo), "f"(hi)); return r;
}
__device__ __forceinline__ void unpack2(float& lo, float& hi, u64 v) {
    asm("mov.b64 {%0, %1}, %2;" : "=f"(lo), "=f"(hi) : "l"(v));
}
__device__ __forceinline__ void fma2(u64& d, u64 a, u64 b) {
    asm("fma.rn.f32x2 %0, %1, %2, %0;" : "+l"(d) : "l"(a), "l"(b));
}

// ---------------- zero counters ----------------
__global__ void zero_k() {
    int i = blockIdx.x * blockDim.x + threadIdx.x;
    if (i < N_NODES) { g_deg_out[i] = 0; g_deg_in[i] = 0; g_fill[i] = 0; }
}

// ---------------- degrees (int atomics) ----------------
__global__ void degree_k(const int* __restrict__ src, const int* __restrict__ dst) {
    int e = blockIdx.x * blockDim.x + threadIdx.x;
    if (e < N_EDGES) {
        atomicAdd(&g_deg_out[src[e]], 1);
        atomicAdd(&g_deg_in[dst[e]], 1);
    }
}

// ---------------- single-block scan of deg_in -> row_ptr ----------------
#define SCAN_T 1024
#define SCAN_CH 40   // 1024*40 = 40960 >= N_NODES
__global__ __launch_bounds__(SCAN_T) void scan_k() {
    __shared__ int ssum[SCAN_T];
    int t = threadIdx.x;
    int base = t * SCAN_CH;
    int s = 0;
#pragma unroll 8
    for (int i = 0; i < SCAN_CH; i++) {
        int idx = base + i;
        if (idx < N_NODES) s += g_deg_in[idx];
    }
    ssum[t] = s;
    __syncthreads();
    // Hillis-Steele inclusive scan
    for (int off = 1; off < SCAN_T; off <<= 1) {
        int v = ssum[t];
        int add = (t >= off) ? ssum[t - off] : 0;
        __syncthreads();
        ssum[t] = v + add;
        __syncthreads();
    }
    int run = (t == 0) ? 0 : ssum[t - 1];   // exclusive prefix
    for (int i = 0; i < SCAN_CH; i++) {
        int idx = base + i;
        if (idx < N_NODES) { g_row_ptr[idx] = run; run += g_deg_in[idx]; }
    }
    if (t == SCAN_T - 1) g_row_ptr[N_NODES] = run;  // == N_EDGES
}

// ---------------- CSR fill ----------------
__global__ void fill_k(const int* __restrict__ src, const int* __restrict__ dst) {
    int e = blockIdx.x * blockDim.x + threadIdx.x;
    if (e < N_EDGES) {
        int d = dst[e];
        int pos = g_row_ptr[d] + atomicAdd(&g_fill[d], 1);
        g_csr_src[pos] = src[e];
    }
}

// ---------------- GEMM: out[M,128] = transform(in)[M,128] @ W[128,128] ----------------
// transform (bprev == null):  v = in * ns(row)
// transform (bprev != null):  v = relu(in * nd(row) + bprev[col]) * ns(row)
#define KC 16
__global__ __launch_bounds__(256) void gemm_k(
    const float* __restrict__ in, const float* __restrict__ W,
    const float* __restrict__ bprev, float* __restrict__ out)
{
    __shared__ float sA[KC][HID + 4];
    __shared__ __align__(16) float sW[KC][HID];
    __shared__ float sNs[HID];
    __shared__ float sNd[HID];

    const int tid = threadIdx.x;
    const int tx = tid & 15;     // 0..15 -> columns
    const int ty = tid >> 4;     // 0..15 -> rows
    const int row0 = blockIdx.x * 128;

    if (tid < 128) {
        int r = row0 + tid;
        float ns = 0.f, nd = 0.f;
        if (r < N_NODES) {
            ns = rsqrtf(fmaxf((float)g_deg_out[r], 1.f));
            nd = rsqrtf(fmaxf((float)g_deg_in[r], 1.f));
        }
        sNs[tid] = ns;
        sNd[tid] = nd;
    }
    __syncthreads();

    u64 acc2[8][4];
#pragma unroll
    for (int i = 0; i < 8; i++)
#pragma unroll
        for (int j = 0; j < 4; j++) acc2[i][j] = 0ull;

    for (int k0 = 0; k0 < HID; k0 += KC) {
        // load A tile (128 rows x 16 k), transposed into sA[k][row], transform fused
#pragma unroll
        for (int t = 0; t < 2; t++) {
            int l = tid + t * 256;        // 0..511
            int r = l >> 2;               // 0..127
            int kq = (l & 3) * 4;         // 0,4,8,12
            int grow = row0 + r;
            float4 v = make_float4(0.f, 0.f, 0.f, 0.f);
            if (grow < N_NODES) {
                v = *(const float4*)&in[grow * HID + k0 + kq];
                float ns = sNs[r];
                if (bprev) {
                    float nd = sNd[r];
                    float4 b = *(const float4*)&bprev[k0 + kq];
                    v.x = fmaxf(v.x * nd + b.x, 0.f);
                    v.y = fmaxf(v.y * nd + b.y, 0.f);
                    v.z = fmaxf(v.z * nd + b.z, 0.f);
                    v.w = fmaxf(v.w * nd + b.w, 0.f);
                }
                v.x *= ns; v.y *= ns; v.z *= ns; v.w *= ns;
            }
            sA[kq + 0][r] = v.x;
            sA[kq + 1][r] = v.y;
            sA[kq + 2][r] = v.z;
            sA[kq + 3][r] = v.w;
        }
        // load W tile (16 k x 128 cols)
#pragma unroll
        for (int t = 0; t < 2; t++) {
            int l = tid + t * 256;        // 0..511
            int kk = l >> 5;              // 0..15
            int n4 = (l & 31) * 4;        // 0..124
            *(float4*)&sW[kk][n4] = *(const float4*)&W[(k0 + kk) * HID + n4];
        }
        __syncthreads();

#pragma unroll
        for (int kk = 0; kk < KC; kk++) {
            float4 a0 = *(const float4*)&sA[kk][ty * 4];
            float4 a1 = *(const float4*)&sA[kk][ty * 4 + 64];
            // w pairs straight out of shared as 64-bit lanes
            const u64* wrow = (const u64*)&sW[kk][0];
            u64 w0 = wrow[tx * 2];
            u64 w1 = wrow[tx * 2 + 1];
            u64 w2 = wrow[tx * 2 + 32];
            u64 w3 = wrow[tx * 2 + 33];
            float a[8] = {a0.x, a0.y, a0.z, a0.w, a1.x, a1.y, a1.z, a1.w};
#pragma unroll
            for (int i = 0; i < 8; i++) {
                u64 aa = pack2(a[i], a[i]);
                fma2(acc2[i][0], aa, w0);
                fma2(acc2[i][1], aa, w1);
                fma2(acc2[i][2], aa, w2);
                fma2(acc2[i][3], aa, w3);
            }
        }
        __syncthreads();
    }

    // epilogue
#pragma unroll
    for (int i = 0; i < 8; i++) {
        int r = row0 + ((i < 4) ? (ty * 4 + i) : (ty * 4 + 64 + i - 4));
        if (r >= N_NODES) continue;
        float4 c0, c1;
        unpack2(c0.x, c0.y, acc2[i][0]);
        unpack2(c0.z, c0.w, acc2[i][1]);
        unpack2(c1.x, c1.y, acc2[i][2]);
        unpack2(c1.z, c1.w, acc2[i][3]);
        *(float4*)&out[r * HID + tx * 4] = c0;
        *(float4*)&out[r * HID + tx * 4 + 64] = c1;
    }
}

// ---------------- gather: agg[n] = sum_{e: dst==n} hw[src[e]]  (one warp per node) ----------------
__global__ __launch_bounds__(256) void gather_k(
    const float* __restrict__ hw, float* __restrict__ agg)
{
    int w = (blockIdx.x * blockDim.x + threadIdx.x) >> 5;
    int lane = threadIdx.x & 31;
    if (w >= N_NODES) return;
    int beg = g_row_ptr[w], end = g_row_ptr[w + 1];
    float4 acc = make_float4(0.f, 0.f, 0.f, 0.f);
    int i = beg;
    // 4-way unrolled for memory-level parallelism
    for (; i + 3 < end; i += 4) {
        int s0 = g_csr_src[i + 0];
        int s1 = g_csr_src[i + 1];
        int s2 = g_csr_src[i + 2];
        int s3 = g_csr_src[i + 3];
        float4 v0 = *(const float4*)&hw[s0 * HID + lane * 4];
        float4 v1 = *(const float4*)&hw[s1 * HID + lane * 4];
        float4 v2 = *(const float4*)&hw[s2 * HID + lane * 4];
        float4 v3 = *(const float4*)&hw[s3 * HID + lane * 4];
        acc.x += (v0.x + v1.x) + (v2.x + v3.x);
        acc.y += (v0.y + v1.y) + (v2.y + v3.y);
        acc.z += (v0.z + v1.z) + (v2.z + v3.z);
        acc.w += (v0.w + v1.w) + (v2.w + v3.w);
    }
    for (; i < end; i++) {
        int s = g_csr_src[i];
        float4 v = *(const float4*)&hw[s * HID + lane * 4];
        acc.x += v.x; acc.y += v.y; acc.z += v.z; acc.w += v.w;
    }
    *(float4*)&agg[w * HID + lane * 4] = acc;
}

// ---------------- fused pool + MLP head: one block per graph (graph_ids sorted!) ----------------
__global__ __launch_bounds__(128) void head_k(
    const float* __restrict__ agg2, const float* __restrict__ b2,
    const int* __restrict__ gid,
    const float* __restrict__ Wc1, const float* __restrict__ bc1,
    const float* __restrict__ Wc2, const float* __restrict__ bc2,
    const float* __restrict__ Wc3, const float* __restrict__ bc3,
    float* __restrict__ out)
{
    int g = blockIdx.x;
    int j = threadIdx.x;
    __shared__ int sRange[2];
    __shared__ float sIn[HID];
    __shared__ float sMid[HID];
    __shared__ float red[4];

    if (j < 2) {
        // lower_bound of (g + j) in sorted gid
        int target = g + j;
        int lo = 0, hi = N_NODES;
        while (lo < hi) {
            int mid = (lo + hi) >> 1;
            if (gid[mid] < target) lo = mid + 1; else hi = mid;
        }
        sRange[j] = lo;
    }
    __syncthreads();
    int beg = sRange[0], end = sRange[1];

    float bj = b2[j];
    float acc = 0.f;
    for (int n = beg; n < end; n++) {
        float nd = rsqrtf(fmaxf((float)g_deg_in[n], 1.f));
        acc += fmaxf(agg2[n * HID + j] * nd + bj, 0.f);
    }
    float cnt = (float)(end - beg);
    sIn[j] = acc / fmaxf(cnt, 1.f);
    __syncthreads();

    float a = bc1[j];
#pragma unroll 4
    for (int k = 0; k < HID; k++) a += sIn[k] * Wc1[k * HID + j];
    sMid[j] = fmaxf(a, 0.f);
    __syncthreads();

    float b = bc2[j];
#pragma unroll 4
    for (int k = 0; k < HID; k++) b += sMid[k] * Wc2[k * HID + j];
    b = fmaxf(b, 0.f);

    float p = b * Wc3[j];
#pragma unroll
    for (int o = 16; o > 0; o >>= 1) p += __shfl_down_sync(0xffffffffu, p, o);
    if ((j & 31) == 0) red[j >> 5] = p;
    __syncthreads();
    if (j == 0) out[g] = red[0] + red[1] + red[2] + red[3] + bc3[0];
}

// ---------------- launch ----------------
extern "C" void kernel_launch(void* const* d_in, const int* in_sizes, int n_in,
                              void* d_out, int out_size)
{
    const float* h   = (const float*)d_in[0];
    const int* src   = (const int*)d_in[1];
    const int* dst   = (const int*)d_in[2];
    const int* gid   = (const int*)d_in[3];
    const float* W1  = (const float*)d_in[4];
    const float* b1  = (const float*)d_in[5];
    const float* W2  = (const float*)d_in[6];
    const float* b2  = (const float*)d_in[7];
    const float* Wc1 = (const float*)d_in[8];
    const float* bc1 = (const float*)d_in[9];
    const float* Wc2 = (const float*)d_in[10];
    const float* bc2 = (const float*)d_in[11];
    const float* Wc3 = (const float*)d_in[12];
    const float* bc3 = (const float*)d_in[13];
    float* out = (float*)d_out;

    float *pA, *pB, *pC;
    cudaGetSymbolAddress((void**)&pA, g_bufA);
    cudaGetSymbolAddress((void**)&pB, g_bufB);
    cudaGetSymbolAddress((void**)&pC, g_bufC);

    // CSR build
    zero_k<<<(N_NODES + 255) / 256, 256>>>();
    degree_k<<<(N_EDGES + 255) / 256, 256>>>(src, dst);
    scan_k<<<1, SCAN_T>>>();
    fill_k<<<(N_EDGES + 255) / 256, 256>>>(src, dst);

    const int gemm_blocks = (N_NODES + 127) / 128;          // 313
    const int gath_blocks = (N_NODES * 32 + 255) / 256;     // 5000

    // layer 1
    gemm_k<<<gemm_blocks, 256>>>(h, W1, nullptr, pA);
    gather_k<<<gath_blocks, 256>>>(pA, pB);

    // layer 2 (relu(agg1*nd+b1)*ns fused into loader)
    gemm_k<<<gemm_blocks, 256>>>(pB, W2, b1, pA);
    gather_k<<<gath_blocks, 256>>>(pA, pC);

    // fused pool + head
    head_k<<<N_GRAPHS, 128>>>(pC, b2, gid, Wc1, bc1, Wc2, bc2, Wc3, bc3, out);
}

// round 6
// speedup vs baseline: 2.2399x; 1.0003x over previous
#include <cuda_runtime.h>
#include <cuda_bf16.h>

#define N_NODES  40000
#define N_EDGES  640000
#define HID      128
#define N_GRAPHS 256

typedef unsigned long long u64;

// ---------------- scratch (no allocation allowed) ----------------
__device__ float g_bufA[N_NODES * HID];   // hw (gemm output)
__device__ float g_bufB[N_NODES * HID];   // agg layer 1
__device__ float g_bufC[N_NODES * HID];   // agg layer 2
__device__ int   g_deg_out[N_NODES];
__device__ int   g_deg_in[N_NODES];
__device__ int   g_row_ptr[N_NODES + 1];
__device__ int   g_fill[N_NODES];
__device__ int   g_csr_src[N_EDGES];

// ---------------- f32x2 helpers ----------------
__device__ __forceinline__ u64 pack2(float lo, float hi) {
    u64 r; asm("mov.b64 %0, {%1, %2};" : "=l"(r) : "f"(lo), "f"(hi)); return r;
}
__device__ __forceinline__ void unpack2(float& lo, float& hi, u64 v) {
    asm("mov.b64 {%0, %1}, %2;" : "=f"(lo), "=f"(hi) : "l"(v));
}
__device__ __forceinline__ void fma2(u64& d, u64 a, u64 b) {
    asm("fma.rn.f32x2 %0, %1, %2, %0;" : "+l"(d) : "l"(a), "l"(b));
}

// ---------------- zero counters ----------------
__global__ void zero_k() {
    int i = blockIdx.x * blockDim.x + threadIdx.x;
    if (i < N_NODES) { g_deg_out[i] = 0; g_deg_in[i] = 0; g_fill[i] = 0; }
}

// ---------------- degrees (int atomics) ----------------
__global__ void degree_k(const int* __restrict__ src, const int* __restrict__ dst) {
    int e = blockIdx.x * blockDim.x + threadIdx.x;
    if (e < N_EDGES) {
        atomicAdd(&g_deg_out[src[e]], 1);
        atomicAdd(&g_deg_in[dst[e]], 1);
    }
}

// ---------------- single-block scan of deg_in -> row_ptr ----------------
#define SCAN_T 1024
#define SCAN_CH 40   // 1024*40 = 40960 >= N_NODES
__global__ __launch_bounds__(SCAN_T) void scan_k() {
    __shared__ int ssum[SCAN_T];
    int t = threadIdx.x;
    int base = t * SCAN_CH;
    int s = 0;
#pragma unroll 8
    for (int i = 0; i < SCAN_CH; i++) {
        int idx = base + i;
        if (idx < N_NODES) s += g_deg_in[idx];
    }
    ssum[t] = s;
    __syncthreads();
    // Hillis-Steele inclusive scan
    for (int off = 1; off < SCAN_T; off <<= 1) {
        int v = ssum[t];
        int add = (t >= off) ? ssum[t - off] : 0;
        __syncthreads();
        ssum[t] = v + add;
        __syncthreads();
    }
    int run = (t == 0) ? 0 : ssum[t - 1];   // exclusive prefix
    for (int i = 0; i < SCAN_CH; i++) {
        int idx = base + i;
        if (idx < N_NODES) { g_row_ptr[idx] = run; run += g_deg_in[idx]; }
    }
    if (t == SCAN_T - 1) g_row_ptr[N_NODES] = run;  // == N_EDGES
}

// ---------------- CSR fill ----------------
__global__ void fill_k(const int* __restrict__ src, const int* __restrict__ dst) {
    int e = blockIdx.x * blockDim.x + threadIdx.x;
    if (e < N_EDGES) {
        int d = dst[e];
        int pos = g_row_ptr[d] + atomicAdd(&g_fill[d], 1);
        g_csr_src[pos] = src[e];
    }
}

// ---------------- GEMM: out[M,128] = transform(in)[M,128] @ W[128,128] ----------------
// transform (bprev == null):  v = in * ns(row)
// transform (bprev != null):  v = relu(in * nd(row) + bprev[col]) * ns(row)
#define KC 16
__global__ __launch_bounds__(256) void gemm_k(
    const float* __restrict__ in, const float* __restrict__ W,
    const float* __restrict__ bprev, float* __restrict__ out)
{
    __shared__ float sA[KC][HID + 4];
    __shared__ __align__(16) float sW[KC][HID];
    __shared__ float sNs[HID];
    __shared__ float sNd[HID];

    const int tid = threadIdx.x;
    const int tx = tid & 15;     // 0..15 -> columns
    const int ty = tid >> 4;     // 0..15 -> rows
    const int row0 = blockIdx.x * 128;

    if (tid < 128) {
        int r = row0 + tid;
        float ns = 0.f, nd = 0.f;
        if (r < N_NODES) {
            ns = rsqrtf(fmaxf((float)g_deg_out[r], 1.f));
            nd = rsqrtf(fmaxf((float)g_deg_in[r], 1.f));
        }
        sNs[tid] = ns;
        sNd[tid] = nd;
    }
    __syncthreads();

    u64 acc2[8][4];
#pragma unroll
    for (int i = 0; i < 8; i++)
#pragma unroll
        for (int j = 0; j < 4; j++) acc2[i][j] = 0ull;

    for (int k0 = 0; k0 < HID; k0 += KC) {
        // load A tile (128 rows x 16 k), transposed into sA[k][row], transform fused
#pragma unroll
        for (int t = 0; t < 2; t++) {
            int l = tid + t * 256;        // 0..511
            int r = l >> 2;               // 0..127
            int kq = (l & 3) * 4;         // 0,4,8,12
            int grow = row0 + r;
            float4 v = make_float4(0.f, 0.f, 0.f, 0.f);
            if (grow < N_NODES) {
                v = *(const float4*)&in[grow * HID + k0 + kq];
                float ns = sNs[r];
                if (bprev) {
                    float nd = sNd[r];
                    float4 b = *(const float4*)&bprev[k0 + kq];
                    v.x = fmaxf(v.x * nd + b.x, 0.f);
                    v.y = fmaxf(v.y * nd + b.y, 0.f);
                    v.z = fmaxf(v.z * nd + b.z, 0.f);
                    v.w = fmaxf(v.w * nd + b.w, 0.f);
                }
                v.x *= ns; v.y *= ns; v.z *= ns; v.w *= ns;
            }
            sA[kq + 0][r] = v.x;
            sA[kq + 1][r] = v.y;
            sA[kq + 2][r] = v.z;
            sA[kq + 3][r] = v.w;
        }
        // load W tile (16 k x 128 cols)
#pragma unroll
        for (int t = 0; t < 2; t++) {
            int l = tid + t * 256;        // 0..511
            int kk = l >> 5;              // 0..15
            int n4 = (l & 31) * 4;        // 0..124
            *(float4*)&sW[kk][n4] = *(const float4*)&W[(k0 + kk) * HID + n4];
        }
        __syncthreads();

#pragma unroll
        for (int kk = 0; kk < KC; kk++) {
            float4 a0 = *(const float4*)&sA[kk][ty * 4];
            float4 a1 = *(const float4*)&sA[kk][ty * 4 + 64];
            // w pairs straight out of shared as 64-bit lanes
            const u64* wrow = (const u64*)&sW[kk][0];
            u64 w0 = wrow[tx * 2];
            u64 w1 = wrow[tx * 2 + 1];
            u64 w2 = wrow[tx * 2 + 32];
            u64 w3 = wrow[tx * 2 + 33];
            float a[8] = {a0.x, a0.y, a0.z, a0.w, a1.x, a1.y, a1.z, a1.w};
#pragma unroll
            for (int i = 0; i < 8; i++) {
                u64 aa = pack2(a[i], a[i]);
                fma2(acc2[i][0], aa, w0);
                fma2(acc2[i][1], aa, w1);
                fma2(acc2[i][2], aa, w2);
                fma2(acc2[i][3], aa, w3);
            }
        }
        __syncthreads();
    }

    // epilogue
#pragma unroll
    for (int i = 0; i < 8; i++) {
        int r = row0 + ((i < 4) ? (ty * 4 + i) : (ty * 4 + 64 + i - 4));
        if (r >= N_NODES) continue;
        float4 c0, c1;
        unpack2(c0.x, c0.y, acc2[i][0]);
        unpack2(c0.z, c0.w, acc2[i][1]);
        unpack2(c1.x, c1.y, acc2[i][2]);
        unpack2(c1.z, c1.w, acc2[i][3]);
        *(float4*)&out[r * HID + tx * 4] = c0;
        *(float4*)&out[r * HID + tx * 4 + 64] = c1;
    }
}

// ---------------- gather: agg[n] = sum_{e: dst==n} hw[src[e]]  (one warp per node) ----------------
__global__ __launch_bounds__(256) void gather_k(
    const float* __restrict__ hw, float* __restrict__ agg)
{
    int w = (blockIdx.x * blockDim.x + threadIdx.x) >> 5;
    int lane = threadIdx.x & 31;
    if (w >= N_NODES) return;
    int beg = g_row_ptr[w], end = g_row_ptr[w + 1];
    float4 acc = make_float4(0.f, 0.f, 0.f, 0.f);
    int i = beg;
    // 4-way unrolled for memory-level parallelism
    for (; i + 3 < end; i += 4) {
        int s0 = g_csr_src[i + 0];
        int s1 = g_csr_src[i + 1];
        int s2 = g_csr_src[i + 2];
        int s3 = g_csr_src[i + 3];
        float4 v0 = *(const float4*)&hw[s0 * HID + lane * 4];
        float4 v1 = *(const float4*)&hw[s1 * HID + lane * 4];
        float4 v2 = *(const float4*)&hw[s2 * HID + lane * 4];
        float4 v3 = *(const float4*)&hw[s3 * HID + lane * 4];
        acc.x += (v0.x + v1.x) + (v2.x + v3.x);
        acc.y += (v0.y + v1.y) + (v2.y + v3.y);
        acc.z += (v0.z + v1.z) + (v2.z + v3.z);
        acc.w += (v0.w + v1.w) + (v2.w + v3.w);
    }
    for (; i < end; i++) {
        int s = g_csr_src[i];
        float4 v = *(const float4*)&hw[s * HID + lane * 4];
        acc.x += v.x; acc.y += v.y; acc.z += v.z; acc.w += v.w;
    }
    *(float4*)&agg[w * HID + lane * 4] = acc;
}

// ---------------- fused pool + MLP head: one block per graph (graph_ids sorted!) ----------------
__global__ __launch_bounds__(128) void head_k(
    const float* __restrict__ agg2, const float* __restrict__ b2,
    const int* __restrict__ gid,
    const float* __restrict__ Wc1, const float* __restrict__ bc1,
    const float* __restrict__ Wc2, const float* __restrict__ bc2,
    const float* __restrict__ Wc3, const float* __restrict__ bc3,
    float* __restrict__ out)
{
    int g = blockIdx.x;
    int j = threadIdx.x;
    __shared__ int sRange[2];
    __shared__ float sIn[HID];
    __shared__ float sMid[HID];
    __shared__ float red[4];

    if (j < 2) {
        // lower_bound of (g + j) in sorted gid
        int target = g + j;
        int lo = 0, hi = N_NODES;
        while (lo < hi) {
            int mid = (lo + hi) >> 1;
            if (gid[mid] < target) lo = mid + 1; else hi = mid;
        }
        sRange[j] = lo;
    }
    __syncthreads();
    int beg = sRange[0], end = sRange[1];

    float bj = b2[j];
    float acc = 0.f;
    for (int n = beg; n < end; n++) {
        float nd = rsqrtf(fmaxf((float)g_deg_in[n], 1.f));
        acc += fmaxf(agg2[n * HID + j] * nd + bj, 0.f);
    }
    float cnt = (float)(end - beg);
    sIn[j] = acc / fmaxf(cnt, 1.f);
    __syncthreads();

    float a = bc1[j];
#pragma unroll 4
    for (int k = 0; k < HID; k++) a += sIn[k] * Wc1[k * HID + j];
    sMid[j] = fmaxf(a, 0.f);
    __syncthreads();

    float b = bc2[j];
#pragma unroll 4
    for (int k = 0; k < HID; k++) b += sMid[k] * Wc2[k * HID + j];
    b = fmaxf(b, 0.f);

    float p = b * Wc3[j];
#pragma unroll
    for (int o = 16; o > 0; o >>= 1) p += __shfl_down_sync(0xffffffffu, p, o);
    if ((j & 31) == 0) red[j >> 5] = p;
    __syncthreads();
    if (j == 0) out[g] = red[0] + red[1] + red[2] + red[3] + bc3[0];
}

// ---------------- launch ----------------
extern "C" void kernel_launch(void* const* d_in, const int* in_sizes, int n_in,
                              void* d_out, int out_size)
{
    const float* h   = (const float*)d_in[0];
    const int* src   = (const int*)d_in[1];
    const int* dst   = (const int*)d_in[2];
    const int* gid   = (const int*)d_in[3];
    const float* W1  = (const float*)d_in[4];
    const float* b1  = (const float*)d_in[5];
    const float* W2  = (const float*)d_in[6];
    const float* b2  = (const float*)d_in[7];
    const float* Wc1 = (const float*)d_in[8];
    const float* bc1 = (const float*)d_in[9];
    const float* Wc2 = (const float*)d_in[10];
    const float* bc2 = (const float*)d_in[11];
    const float* Wc3 = (const float*)d_in[12];
    const float* bc3 = (const float*)d_in[13];
    float* out = (float*)d_out;

    float *pA, *pB, *pC;
    cudaGetSymbolAddress((void**)&pA, g_bufA);
    cudaGetSymbolAddress((void**)&pB, g_bufB);
    cudaGetSymbolAddress((void**)&pC, g_bufC);

    // CSR build
    zero_k<<<(N_NODES + 255) / 256, 256>>>();
    degree_k<<<(N_EDGES + 255) / 256, 256>>>(src, dst);
    scan_k<<<1, SCAN_T>>>();
    fill_k<<<(N_EDGES + 255) / 256, 256>>>(src, dst);

    const int gemm_blocks = (N_NODES + 127) / 128;          // 313
    const int gath_blocks = (N_NODES * 32 + 255) / 256;     // 5000

    // layer 1
    gemm_k<<<gemm_blocks, 256>>>(h, W1, nullptr, pA);
    gather_k<<<gath_blocks, 256>>>(pA, pB);

    // layer 2 (relu(agg1*nd+b1)*ns fused into loader)
    gemm_k<<<gemm_blocks, 256>>>(pB, W2, b1, pA);
    gather_k<<<gath_blocks, 256>>>(pA, pC);

    // fused pool + head
    head_k<<<N_GRAPHS, 128>>>(pC, b2, gid, Wc1, bc1, Wc2, bc2, Wc3, bc3, out);
}